// round 3
// baseline (speedup 1.0000x reference)
#include <cuda_runtime.h>
#include <math.h>

#define NN 150000
#define EE 2400000
#define BB 16384
#define N_USERS 100000
#define EMB 64
#define HID 128
#define LN_EPS 1e-5f
#define NBLKS 147   // ceil(NN/1024)
#define H1S 132     // padded h1 tile row stride (banks: 4*132 % 32 = 16 -> broadcast-safe)

// ---------------- static scratch ----------------
__device__ float d_xs [(size_t)NN * 64];    // dinv[n] * x[n]
__device__ float d_ax [(size_t)NN * 64];    // A_hat @ x
__device__ float d_xs2[(size_t)NN * 64];    // dinv[n] * (relu(ax W1 + b1) @ W2)[n]
__device__ float d_h2 [(size_t)NN * 64];    // layer-2 output
__device__ int   d_counts[NN];
__device__ int   d_rowstart[NN];
__device__ int   d_cursor[NN];
__device__ float d_dinv[NN];
__device__ int   d_csrsrc[EE];
__device__ int   d_bsum[256];

// ---------------- CSR build ----------------
__global__ void k_zero_counts() {
    int i = blockIdx.x * blockDim.x + threadIdx.x;
    if (i < NN) d_counts[i] = 0;
}

__global__ void k_count(const int* __restrict__ dst) {
    int e = blockIdx.x * blockDim.x + threadIdx.x;
    if (e < EE) atomicAdd(&d_counts[dst[e]], 1);
}

// block-level exclusive scan via warp shuffles (1024 threads = 32 warps)
__global__ void k_scan1() {
    __shared__ int wsum[32];
    int t = threadIdx.x;
    int i = blockIdx.x * 1024 + t;
    int v = (i < NN) ? d_counts[i] : 0;
    int lane = t & 31, w = t >> 5;
    int x = v;
    #pragma unroll
    for (int o = 1; o < 32; o <<= 1) {
        int y = __shfl_up_sync(0xffffffffu, x, o);
        if (lane >= o) x += y;
    }
    if (lane == 31) wsum[w] = x;
    __syncthreads();
    if (w == 0) {
        int s = wsum[lane];
        #pragma unroll
        for (int o = 1; o < 32; o <<= 1) {
            int y = __shfl_up_sync(0xffffffffu, s, o);
            if (lane >= o) s += y;
        }
        wsum[lane] = s;
    }
    __syncthreads();
    int incl = x + ((w > 0) ? wsum[w - 1] : 0);
    if (i < NN) d_rowstart[i] = incl - v;
    if (t == 1023) d_bsum[blockIdx.x] = incl;
}

// single-warp exclusive scan over the 147 block sums
__global__ void k_scan2() {
    int lane = threadIdx.x;
    int vals[5];
    int s = 0;
    #pragma unroll
    for (int j = 0; j < 5; j++) {
        int idx = lane * 5 + j;
        vals[j] = (idx < NBLKS) ? d_bsum[idx] : 0;
        s += vals[j];
    }
    int x = s;
    #pragma unroll
    for (int o = 1; o < 32; o <<= 1) {
        int y = __shfl_up_sync(0xffffffffu, x, o);
        if (lane >= o) x += y;
    }
    int run = x - s;   // exclusive prefix of this lane's chunk
    #pragma unroll
    for (int j = 0; j < 5; j++) {
        int idx = lane * 5 + j;
        if (idx < NBLKS) d_bsum[idx] = run;
        run += vals[j];
    }
}

__global__ void k_scan3() {
    int i = blockIdx.x * blockDim.x + threadIdx.x;
    if (i < NN) {
        int rs = d_rowstart[i] + d_bsum[i >> 10];
        d_rowstart[i] = rs;
        d_cursor[i]   = rs;
        d_dinv[i]     = rsqrtf(1.0f + (float)d_counts[i]);
    }
}

__global__ void k_fill(const int* __restrict__ src, const int* __restrict__ dst) {
    int e = blockIdx.x * blockDim.x + threadIdx.x;
    if (e < EE) {
        int d = dst[e];
        int p = atomicAdd(&d_cursor[d], 1);
        d_csrsrc[p] = src[e];
    }
}

// ---------------- prescale: xs = dinv[n] * x[n] ----------------
__global__ void k_prescale(const float* __restrict__ x) {
    int i = blockIdx.x * blockDim.x + threadIdx.x;     // float4 index
    if (i < NN * 16) {
        float4 v = ((const float4*)x)[i];
        float di = d_dinv[i >> 4];
        ((float4*)d_xs)[i] = make_float4(v.x * di, v.y * di, v.z * di, v.w * di);
    }
}

// ---------------- aggregation (F=64, warp per node) ----------------
__global__ void k_agg1() {
    int gw   = (blockIdx.x * blockDim.x + threadIdx.x) >> 5;
    int lane = threadIdx.x & 31;
    if (gw >= NN) return;
    int rs  = d_rowstart[gw];
    int cnt = d_counts[gw];
    const float2* base = (const float2*)d_xs;
    float2 self = base[(size_t)gw * 32 + lane];
    float ax = self.x, ay = self.y;
    #pragma unroll 8
    for (int j = 0; j < cnt; j++) {
        int s = __ldg(&d_csrsrc[rs + j]);
        float2 v = base[(size_t)s * 32 + lane];
        ax += v.x; ay += v.y;
    }
    float di = d_dinv[gw];
    ((float2*)d_ax)[(size_t)gw * 32 + lane] = make_float2(di * ax, di * ay);
}

__global__ void k_agg2(const float* __restrict__ b2) {
    int gw   = (blockIdx.x * blockDim.x + threadIdx.x) >> 5;
    int lane = threadIdx.x & 31;
    if (gw >= NN) return;
    int rs  = d_rowstart[gw];
    int cnt = d_counts[gw];
    const float2* base = (const float2*)d_xs2;
    float2 self = base[(size_t)gw * 32 + lane];
    float ax = self.x, ay = self.y;
    #pragma unroll 8
    for (int j = 0; j < cnt; j++) {
        int s = __ldg(&d_csrsrc[rs + j]);
        float2 v = base[(size_t)s * 32 + lane];
        ax += v.x; ay += v.y;
    }
    float di = d_dinv[gw];
    float2 bv = *(const float2*)&b2[lane * 2];
    ((float2*)d_h2)[(size_t)gw * 32 + lane] =
        make_float2(di * ax + bv.x, di * ay + bv.y);
}

// ---------------- fused GEMM: xs2 = dinv * (relu(ax @ W1 + b1) @ W2) -------
// 32-row tile, 128 threads. h1 tile (32x128) lives only in smem.
// Weights read via L1 (each 32KB matrix stays L1-resident per SM).
__global__ __launch_bounds__(128) void k_gemm_fused(const float* __restrict__ W1,
                                                    const float* __restrict__ b1,
                                                    const float* __restrict__ W2) {
    __shared__ float Xs [32 * 64];    // 8 KB
    __shared__ float h1s[32 * H1S];   // 16.5 KB
    int t = threadIdx.x;
    int rowbase = blockIdx.x * 32;

    for (int i = t * 4; i < 32 * 64; i += 512) {
        int row = rowbase + (i >> 6);
        float4 v = (row < NN) ? *(const float4*)&d_ax[(size_t)rowbase * 64 + i]
                              : make_float4(0.f, 0.f, 0.f, 0.f);
        *(float4*)&Xs[i] = v;
    }
    __syncthreads();

    // ---- gemm1: 8 rows x 4 cols per thread -> h1s (bias + relu) ----
    {
        int c = t & 31, rg = t >> 5;
        float4 acc[8];
        #pragma unroll
        for (int r = 0; r < 8; r++) acc[r] = make_float4(0.f, 0.f, 0.f, 0.f);
        #pragma unroll 4
        for (int k = 0; k < 64; k++) {
            float4 b = __ldg((const float4*)&W1[k * 128 + c * 4]);
            #pragma unroll
            for (int r = 0; r < 8; r++) {
                float a = Xs[(rg * 8 + r) * 64 + k];
                acc[r].x = fmaf(a, b.x, acc[r].x);
                acc[r].y = fmaf(a, b.y, acc[r].y);
                acc[r].z = fmaf(a, b.z, acc[r].z);
                acc[r].w = fmaf(a, b.w, acc[r].w);
            }
        }
        float4 bias = __ldg((const float4*)&b1[c * 4]);
        #pragma unroll
        for (int r = 0; r < 8; r++) {
            int row = rg * 8 + r;
            float4 o = make_float4(fmaxf(acc[r].x + bias.x, 0.f),
                                   fmaxf(acc[r].y + bias.y, 0.f),
                                   fmaxf(acc[r].z + bias.z, 0.f),
                                   fmaxf(acc[r].w + bias.w, 0.f));
            *(float4*)&h1s[row * H1S + c * 4] = o;
        }
    }
    __syncthreads();

    // ---- gemm2: 4 rows x 4 cols per thread from h1s ----
    {
        int c = t & 15, rg = t >> 4;
        float4 acc[4];
        #pragma unroll
        for (int r = 0; r < 4; r++) acc[r] = make_float4(0.f, 0.f, 0.f, 0.f);
        #pragma unroll 4
        for (int k = 0; k < 128; k++) {
            float4 b = __ldg((const float4*)&W2[k * 64 + c * 4]);
            #pragma unroll
            for (int r = 0; r < 4; r++) {
                float a = h1s[(rg * 4 + r) * H1S + k];
                acc[r].x = fmaf(a, b.x, acc[r].x);
                acc[r].y = fmaf(a, b.y, acc[r].y);
                acc[r].z = fmaf(a, b.z, acc[r].z);
                acc[r].w = fmaf(a, b.w, acc[r].w);
            }
        }
        #pragma unroll
        for (int r = 0; r < 4; r++) {
            int row = rowbase + rg * 4 + r;
            if (row < NN) {
                float di = d_dinv[row];
                float4 o = make_float4(di * acc[r].x, di * acc[r].y,
                                       di * acc[r].z, di * acc[r].w);
                *(float4*)&d_xs2[(size_t)row * 64 + c * 4] = o;
            }
        }
    }
}

// ---------------- fused gather + MLP head, 4 rows per block ----------------
__global__ __launch_bounds__(128) void k_mlp(
        const int* __restrict__ ui, const int* __restrict__ ii,
        const float* __restrict__ fcW1, const float* __restrict__ fcb1,
        const float* __restrict__ g1,   const float* __restrict__ be1,
        const float* __restrict__ fcW2, const float* __restrict__ fcb2,
        const float* __restrict__ g2,   const float* __restrict__ be2,
        const float* __restrict__ fcW3, const float* __restrict__ fcb3,
        float* __restrict__ out) {
    __shared__ float cs[4][128];
    __shared__ float zs[4][128];
    __shared__ float rS[4][4], rQ[4][4];
    int t = threadIdx.x, lane = t & 31, w = t >> 5;
    int r0 = blockIdx.x * 4;

    for (int i = t; i < 512; i += 128) {
        int r = i >> 7, f = i & 127;
        int row = r0 + r;
        int node = (f < 64) ? (ui[row] - 1) : (ii[row] - 1 + N_USERS);
        cs[r][f] = d_h2[(size_t)node * 64 + (f & 63)];
    }
    __syncthreads();

    float b1v = fcb1[t];
    float accs[4] = {b1v, b1v, b1v, b1v};
    for (int k = 0; k < 128; k++) {
        float wv = fcW1[k * 128 + t];
        accs[0] = fmaf(cs[0][k], wv, accs[0]);
        accs[1] = fmaf(cs[1][k], wv, accs[1]);
        accs[2] = fmaf(cs[2][k], wv, accs[2]);
        accs[3] = fmaf(cs[3][k], wv, accs[3]);
    }
    #pragma unroll
    for (int r = 0; r < 4; r++) {
        float a = accs[r], q = accs[r] * accs[r];
        #pragma unroll
        for (int o = 16; o; o >>= 1) {
            a += __shfl_xor_sync(0xffffffffu, a, o);
            q += __shfl_xor_sync(0xffffffffu, q, o);
        }
        if (lane == 0) { rS[r][w] = a; rQ[r][w] = q; }
    }
    __syncthreads();
    float g1v = g1[t], be1v = be1[t];
    #pragma unroll
    for (int r = 0; r < 4; r++) {
        float S = rS[r][0] + rS[r][1] + rS[r][2] + rS[r][3];
        float Q = rQ[r][0] + rQ[r][1] + rQ[r][2] + rQ[r][3];
        float mean = S * (1.0f / 128.0f);
        float var  = Q * (1.0f / 128.0f) - mean * mean;
        float z = fmaxf((accs[r] - mean) * rsqrtf(var + LN_EPS) * g1v + be1v, 0.f);
        zs[r][t] = z;
    }
    __syncthreads();

    int c2 = t & 63;
    int rp = (t >> 6) * 2;
    float b2v = fcb2[c2];
    float es[2] = {b2v, b2v};
    for (int k = 0; k < 128; k++) {
        float wv = fcW2[k * 64 + c2];
        es[0] = fmaf(zs[rp][k],     wv, es[0]);
        es[1] = fmaf(zs[rp + 1][k], wv, es[1]);
    }
    #pragma unroll
    for (int i = 0; i < 2; i++) {
        float a = es[i], q = es[i] * es[i];
        #pragma unroll
        for (int o = 16; o; o >>= 1) {
            a += __shfl_xor_sync(0xffffffffu, a, o);
            q += __shfl_xor_sync(0xffffffffu, q, o);
        }
        if (lane == 0) { rS[rp + i][w] = a; rQ[rp + i][w] = q; }
    }
    __syncthreads();
    int wb = (t >> 6) * 2;
    float g2v = g2[c2], be2v = be2[c2], w3 = fcW3[c2];
    float p[2];
    #pragma unroll
    for (int i = 0; i < 2; i++) {
        float S = rS[rp + i][wb] + rS[rp + i][wb + 1];
        float Q = rQ[rp + i][wb] + rQ[rp + i][wb + 1];
        float mean = S * (1.0f / 64.0f);
        float var  = Q * (1.0f / 64.0f) - mean * mean;
        float z2 = fmaxf((es[i] - mean) * rsqrtf(var + LN_EPS) * g2v + be2v, 0.f);
        p[i] = z2 * w3;
    }
    __syncthreads();
    #pragma unroll
    for (int i = 0; i < 2; i++) {
        float a = p[i];
        #pragma unroll
        for (int o = 16; o; o >>= 1)
            a += __shfl_xor_sync(0xffffffffu, a, o);
        if (lane == 0) rS[rp + i][w] = a;
    }
    __syncthreads();
    if (t < 4) {
        int wg = (t >> 1) * 2;
        float s = rS[t][wg] + rS[t][wg + 1] + fcb3[0];
        out[r0 + t] = 1.0f / (1.0f + expf(-s));
    }
}

// ---------------- launch ----------------
extern "C" void kernel_launch(void* const* d_in, const int* in_sizes, int n_in,
                              void* d_out, int out_size) {
    const float* x    = (const float*)d_in[0];
    const int*   src  = (const int*)  d_in[1];
    const int*   dst  = (const int*)  d_in[2];
    const int*   uidx = (const int*)  d_in[3];
    const int*   iidx = (const int*)  d_in[4];
    const float* W1   = (const float*)d_in[5];
    const float* b1   = (const float*)d_in[6];
    const float* W2   = (const float*)d_in[7];
    const float* b2   = (const float*)d_in[8];
    const float* fcW1 = (const float*)d_in[9];
    const float* fcb1 = (const float*)d_in[10];
    const float* g1   = (const float*)d_in[11];
    const float* be1  = (const float*)d_in[12];
    const float* fcW2 = (const float*)d_in[13];
    const float* fcb2 = (const float*)d_in[14];
    const float* g2   = (const float*)d_in[15];
    const float* be2  = (const float*)d_in[16];
    const float* fcW3 = (const float*)d_in[17];
    const float* fcb3 = (const float*)d_in[18];
    float* out = (float*)d_out;

    // CSR build
    k_zero_counts<<<(NN + 511) / 512, 512>>>();
    k_count<<<(EE + 255) / 256, 256>>>(dst);
    k_scan1<<<NBLKS, 1024>>>();
    k_scan2<<<1, 32>>>();
    k_scan3<<<(NN + 511) / 512, 512>>>();
    k_fill<<<(EE + 255) / 256, 256>>>(src, dst);

    // layer 1: aggregate first (F=64), then fused projection 64->128->64
    k_prescale<<<(NN * 16 + 255) / 256, 256>>>(x);
    k_agg1<<<(NN * 32 + 255) / 256, 256>>>();
    k_gemm_fused<<<(NN + 31) / 32, 128>>>(W1, b1, W2);

    // layer 2 aggregation
    k_agg2<<<(NN * 32 + 255) / 256, 256>>>(b2);

    // MLP head (4 pairs per block)
    k_mlp<<<BB / 4, 128>>>(uidx, iidx, fcW1, fcb1, g1, be1,
                           fcW2, fcb2, g2, be2, fcW3, fcb3, out);
}

// round 4
// speedup vs baseline: 1.3495x; 1.3495x over previous
#include <cuda_runtime.h>
#include <math.h>

#define NN 150000
#define EE 2400000
#define BB 16384
#define N_USERS 100000
#define EMB 64
#define HID 128
#define LN_EPS 1e-5f
#define NBLKS 147   // ceil(NN/1024)

// ---------------- static scratch ----------------
__device__ float d_xs [(size_t)NN * 64];    // dinv[n] * x[n]
__device__ float d_ax [(size_t)NN * 64];    // A_hat @ x
__device__ float d_h1 [(size_t)NN * 128];   // relu((A_hat x) W1 + b1)
__device__ float d_xs2[(size_t)NN * 64];    // dinv[n] * (h1 @ W2)[n]
__device__ int   d_counts[NN];
__device__ int   d_rowstart[NN];
__device__ int   d_cursor[NN];
__device__ float d_dinv[NN];
__device__ int   d_csrsrc[EE];
__device__ int   d_bsum[256];

// ---------------- CSR build ----------------
__global__ void k_zero_counts() {
    int i = blockIdx.x * blockDim.x + threadIdx.x;
    if (i < NN) d_counts[i] = 0;
}

__global__ void k_count(const int* __restrict__ dst) {
    int e = blockIdx.x * blockDim.x + threadIdx.x;
    if (e < EE) atomicAdd(&d_counts[dst[e]], 1);
}

__global__ void k_scan1() {
    __shared__ int s[1024];
    int t = threadIdx.x;
    int i = blockIdx.x * 1024 + t;
    int v = (i < NN) ? d_counts[i] : 0;
    s[t] = v;
    __syncthreads();
    for (int off = 1; off < 1024; off <<= 1) {
        int add = (t >= off) ? s[t - off] : 0;
        __syncthreads();
        s[t] += add;
        __syncthreads();
    }
    if (i < NN) d_rowstart[i] = s[t] - v;
    if (t == 1023) d_bsum[blockIdx.x] = s[1023];
}

// parallel exclusive scan over the 147 block sums (single block)
__global__ void k_scan2() {
    __shared__ int s[256];
    int t = threadIdx.x;
    int v = (t < NBLKS) ? d_bsum[t] : 0;
    s[t] = v;
    __syncthreads();
    for (int off = 1; off < 256; off <<= 1) {
        int add = (t >= off) ? s[t - off] : 0;
        __syncthreads();
        s[t] += add;
        __syncthreads();
    }
    if (t < NBLKS) d_bsum[t] = s[t] - v;   // exclusive
}

__global__ void k_scan3() {
    int i = blockIdx.x * blockDim.x + threadIdx.x;
    if (i < NN) {
        int rs = d_rowstart[i] + d_bsum[i >> 10];
        d_rowstart[i] = rs;
        d_cursor[i]   = rs;
        d_dinv[i]     = rsqrtf(1.0f + (float)d_counts[i]);
    }
}

__global__ void k_fill(const int* __restrict__ src, const int* __restrict__ dst) {
    int e = blockIdx.x * blockDim.x + threadIdx.x;
    if (e < EE) {
        int d = dst[e];
        int p = atomicAdd(&d_cursor[d], 1);
        d_csrsrc[p] = src[e];
    }
}

// ---------------- prescale: xs = dinv[n] * x[n] ----------------
__global__ void k_prescale(const float* __restrict__ x) {
    int i = blockIdx.x * blockDim.x + threadIdx.x;     // float4 index
    if (i < NN * 16) {
        float4 v = ((const float4*)x)[i];
        float di = d_dinv[i >> 4];
        ((float4*)d_xs)[i] = make_float4(v.x * di, v.y * di, v.z * di, v.w * di);
    }
}

// ---------------- aggregation layer 1 (F=64, warp per node) ----------------
__global__ void k_agg1() {
    int gw   = (blockIdx.x * blockDim.x + threadIdx.x) >> 5;
    int lane = threadIdx.x & 31;
    if (gw >= NN) return;
    int rs  = d_rowstart[gw];
    int cnt = d_counts[gw];
    const float2* base = (const float2*)d_xs;
    float2 self = base[(size_t)gw * 32 + lane];
    float ax = self.x, ay = self.y;
    #pragma unroll 4
    for (int j = 0; j < cnt; j++) {
        int s = __ldg(&d_csrsrc[rs + j]);
        float2 v = base[(size_t)s * 32 + lane];
        ax += v.x; ay += v.y;
    }
    float di = d_dinv[gw];
    ((float2*)d_ax)[(size_t)gw * 32 + lane] = make_float2(di * ax, di * ay);
}

// ---------------- GEMM1: h1 = relu(ax[N,64] @ W1[64,128] + b1) ----------------
__global__ __launch_bounds__(128) void k_gemm1(const float* __restrict__ W1,
                                               const float* __restrict__ b1) {
    __shared__ float Ws[64 * 128];
    __shared__ float Xs[32 * 64];
    int t = threadIdx.x;
    for (int i = t * 4; i < 64 * 128; i += 512)
        *(float4*)&Ws[i] = *(const float4*)&W1[i];
    int rowbase = blockIdx.x * 32;
    for (int i = t * 4; i < 32 * 64; i += 512) {
        int row = rowbase + (i >> 6);
        float4 v = (row < NN) ? *(const float4*)&d_ax[(size_t)rowbase * 64 + i]
                              : make_float4(0.f, 0.f, 0.f, 0.f);
        *(float4*)&Xs[i] = v;
    }
    __syncthreads();
    int c = t & 31, rg = t >> 5;
    float4 acc[8];
    #pragma unroll
    for (int r = 0; r < 8; r++) acc[r] = make_float4(0.f, 0.f, 0.f, 0.f);
    #pragma unroll 4
    for (int k = 0; k < 64; k++) {
        float4 b = *(float4*)&Ws[k * 128 + c * 4];
        #pragma unroll
        for (int r = 0; r < 8; r++) {
            float a = Xs[(rg * 8 + r) * 64 + k];
            acc[r].x = fmaf(a, b.x, acc[r].x);
            acc[r].y = fmaf(a, b.y, acc[r].y);
            acc[r].z = fmaf(a, b.z, acc[r].z);
            acc[r].w = fmaf(a, b.w, acc[r].w);
        }
    }
    float4 bias = *(const float4*)&b1[c * 4];
    #pragma unroll
    for (int r = 0; r < 8; r++) {
        int row = rowbase + rg * 8 + r;
        if (row < NN) {
            float4 o = make_float4(fmaxf(acc[r].x + bias.x, 0.f),
                                   fmaxf(acc[r].y + bias.y, 0.f),
                                   fmaxf(acc[r].z + bias.z, 0.f),
                                   fmaxf(acc[r].w + bias.w, 0.f));
            *(float4*)&d_h1[(size_t)row * 128 + c * 4] = o;
        }
    }
}

// ---------------- GEMM2: xs2 = dinv * (h1[N,128] @ W2[128,64]) ----------------
__global__ __launch_bounds__(128) void k_gemm2(const float* __restrict__ W2) {
    __shared__ float Ws[128 * 64];
    __shared__ float Xs[32 * 128];
    int t = threadIdx.x;
    for (int i = t * 4; i < 128 * 64; i += 512)
        *(float4*)&Ws[i] = *(const float4*)&W2[i];
    int rowbase = blockIdx.x * 32;
    for (int i = t * 4; i < 32 * 128; i += 512) {
        int row = rowbase + (i >> 7);
        float4 v = (row < NN) ? *(const float4*)&d_h1[(size_t)rowbase * 128 + i]
                              : make_float4(0.f, 0.f, 0.f, 0.f);
        *(float4*)&Xs[i] = v;
    }
    __syncthreads();
    int c = t & 15, rg = t >> 4;
    float4 acc[4];
    #pragma unroll
    for (int r = 0; r < 4; r++) acc[r] = make_float4(0.f, 0.f, 0.f, 0.f);
    #pragma unroll 4
    for (int k = 0; k < 128; k++) {
        float4 b = *(float4*)&Ws[k * 64 + c * 4];
        #pragma unroll
        for (int r = 0; r < 4; r++) {
            float a = Xs[(rg * 4 + r) * 128 + k];
            acc[r].x = fmaf(a, b.x, acc[r].x);
            acc[r].y = fmaf(a, b.y, acc[r].y);
            acc[r].z = fmaf(a, b.z, acc[r].z);
            acc[r].w = fmaf(a, b.w, acc[r].w);
        }
    }
    #pragma unroll
    for (int r = 0; r < 4; r++) {
        int row = rowbase + rg * 4 + r;
        if (row < NN) {
            float di = d_dinv[row];
            float4 o = make_float4(di * acc[r].x, di * acc[r].y,
                                   di * acc[r].z, di * acc[r].w);
            *(float4*)&d_xs2[(size_t)row * 64 + c * 4] = o;
        }
    }
}

// ------- fused layer-2 aggregation + gather + MLP head, 4 rows per block -----
// Aggregates ONLY the <=8 nodes this block needs (user+item per row) directly
// from d_xs2, instead of a full-graph agg2 pass.
__global__ __launch_bounds__(128) void k_mlp(
        const int* __restrict__ ui, const int* __restrict__ ii,
        const float* __restrict__ b2,
        const float* __restrict__ fcW1, const float* __restrict__ fcb1,
        const float* __restrict__ g1,   const float* __restrict__ be1,
        const float* __restrict__ fcW2, const float* __restrict__ fcb2,
        const float* __restrict__ g2,   const float* __restrict__ be2,
        const float* __restrict__ fcW3, const float* __restrict__ fcb3,
        float* __restrict__ out) {
    __shared__ float cs[4][128];
    __shared__ float zs[4][128];
    __shared__ float rS[4][4], rQ[4][4];
    int t = threadIdx.x, lane = t & 31, w = t >> 5;
    int r0 = blockIdx.x * 4;

    // warp w aggregates the user node then the item node for row r0+w
    {
        int row = r0 + w;
        const float2* base = (const float2*)d_xs2;
        float2 bv = ((const float2*)b2)[lane];
        #pragma unroll
        for (int half = 0; half < 2; half++) {
            int node = (half == 0) ? (ui[row] - 1) : (ii[row] - 1 + N_USERS);
            int rs  = d_rowstart[node];
            int cnt = d_counts[node];
            float2 self = base[(size_t)node * 32 + lane];
            float ax = self.x, ay = self.y;
            #pragma unroll 4
            for (int j = 0; j < cnt; j++) {
                int s = __ldg(&d_csrsrc[rs + j]);
                float2 v = base[(size_t)s * 32 + lane];
                ax += v.x; ay += v.y;
            }
            float di = d_dinv[node];
            cs[w][half * 64 + lane * 2]     = di * ax + bv.x;
            cs[w][half * 64 + lane * 2 + 1] = di * ay + bv.y;
        }
    }
    __syncthreads();

    // fc1 [128]->[128], 4 rows
    float b1v = fcb1[t];
    float accs[4] = {b1v, b1v, b1v, b1v};
    for (int k = 0; k < 128; k++) {
        float wv = fcW1[k * 128 + t];
        accs[0] = fmaf(cs[0][k], wv, accs[0]);
        accs[1] = fmaf(cs[1][k], wv, accs[1]);
        accs[2] = fmaf(cs[2][k], wv, accs[2]);
        accs[3] = fmaf(cs[3][k], wv, accs[3]);
    }
    #pragma unroll
    for (int r = 0; r < 4; r++) {
        float a = accs[r], q = accs[r] * accs[r];
        #pragma unroll
        for (int o = 16; o; o >>= 1) {
            a += __shfl_xor_sync(0xffffffffu, a, o);
            q += __shfl_xor_sync(0xffffffffu, q, o);
        }
        if (lane == 0) { rS[r][w] = a; rQ[r][w] = q; }
    }
    __syncthreads();
    float g1v = g1[t], be1v = be1[t];
    #pragma unroll
    for (int r = 0; r < 4; r++) {
        float S = rS[r][0] + rS[r][1] + rS[r][2] + rS[r][3];
        float Q = rQ[r][0] + rQ[r][1] + rQ[r][2] + rQ[r][3];
        float mean = S * (1.0f / 128.0f);
        float var  = Q * (1.0f / 128.0f) - mean * mean;
        float z = fmaxf((accs[r] - mean) * rsqrtf(var + LN_EPS) * g1v + be1v, 0.f);
        zs[r][t] = z;
    }
    __syncthreads();

    // fc2 [128]->[64]
    int c2 = t & 63;
    int rp = (t >> 6) * 2;
    float b2v = fcb2[c2];
    float es[2] = {b2v, b2v};
    for (int k = 0; k < 128; k++) {
        float wv = fcW2[k * 64 + c2];
        es[0] = fmaf(zs[rp][k],     wv, es[0]);
        es[1] = fmaf(zs[rp + 1][k], wv, es[1]);
    }
    #pragma unroll
    for (int i = 0; i < 2; i++) {
        float a = es[i], q = es[i] * es[i];
        #pragma unroll
        for (int o = 16; o; o >>= 1) {
            a += __shfl_xor_sync(0xffffffffu, a, o);
            q += __shfl_xor_sync(0xffffffffu, q, o);
        }
        if (lane == 0) { rS[rp + i][w] = a; rQ[rp + i][w] = q; }
    }
    __syncthreads();
    int wb = (t >> 6) * 2;
    float g2v = g2[c2], be2v = be2[c2], w3 = fcW3[c2];
    float p[2];
    #pragma unroll
    for (int i = 0; i < 2; i++) {
        float S = rS[rp + i][wb] + rS[rp + i][wb + 1];
        float Q = rQ[rp + i][wb] + rQ[rp + i][wb + 1];
        float mean = S * (1.0f / 64.0f);
        float var  = Q * (1.0f / 64.0f) - mean * mean;
        float z2 = fmaxf((es[i] - mean) * rsqrtf(var + LN_EPS) * g2v + be2v, 0.f);
        p[i] = z2 * w3;
    }
    __syncthreads();   // rS reads done before reuse
    #pragma unroll
    for (int i = 0; i < 2; i++) {
        float a = p[i];
        #pragma unroll
        for (int o = 16; o; o >>= 1)
            a += __shfl_xor_sync(0xffffffffu, a, o);
        if (lane == 0) rS[rp + i][w] = a;
    }
    __syncthreads();
    if (t < 4) {
        int wg = (t >> 1) * 2;
        float s = rS[t][wg] + rS[t][wg + 1] + fcb3[0];
        out[r0 + t] = 1.0f / (1.0f + expf(-s));
    }
}

// ---------------- launch ----------------
extern "C" void kernel_launch(void* const* d_in, const int* in_sizes, int n_in,
                              void* d_out, int out_size) {
    const float* x    = (const float*)d_in[0];
    const int*   src  = (const int*)  d_in[1];
    const int*   dst  = (const int*)  d_in[2];
    const int*   uidx = (const int*)  d_in[3];
    const int*   iidx = (const int*)  d_in[4];
    const float* W1   = (const float*)d_in[5];
    const float* b1   = (const float*)d_in[6];
    const float* W2   = (const float*)d_in[7];
    const float* b2   = (const float*)d_in[8];
    const float* fcW1 = (const float*)d_in[9];
    const float* fcb1 = (const float*)d_in[10];
    const float* g1   = (const float*)d_in[11];
    const float* be1  = (const float*)d_in[12];
    const float* fcW2 = (const float*)d_in[13];
    const float* fcb2 = (const float*)d_in[14];
    const float* g2   = (const float*)d_in[15];
    const float* be2  = (const float*)d_in[16];
    const float* fcW3 = (const float*)d_in[17];
    const float* fcb3 = (const float*)d_in[18];
    float* out = (float*)d_out;

    // CSR build
    k_zero_counts<<<(NN + 511) / 512, 512>>>();
    k_count<<<(EE + 255) / 256, 256>>>(dst);
    k_scan1<<<NBLKS, 1024>>>();
    k_scan2<<<1, 256>>>();
    k_scan3<<<(NN + 511) / 512, 512>>>();
    k_fill<<<(EE + 255) / 256, 256>>>(src, dst);

    // layer 1: aggregate first (F=64), then project to 128
    k_prescale<<<(NN * 16 + 255) / 256, 256>>>(x);
    k_agg1<<<(NN * 32 + 255) / 256, 256>>>();
    k_gemm1<<<(NN + 31) / 32, 128>>>(W1, b1);

    // layer 2: project to 64 (with dinv prescale); aggregation happens in k_mlp
    k_gemm2<<<(NN + 31) / 32, 128>>>(W2);

    // fused agg2 + MLP head (4 pairs per block)
    k_mlp<<<BB / 4, 128>>>(uidx, iidx, b2, fcW1, fcb1, g1, be1,
                           fcW2, fcb2, g2, be2, fcW3, fcb3, out);
}